// round 2
// baseline (speedup 1.0000x reference)
#include <cuda_runtime.h>

#define NF  256
#define GS  16
#define NG  16
#define HWS 3136        // 56*56
#define MB  32
#define NTOT (MB*HWS)   // 100352
#define NPAIR 136       // 16*17/2

// Scratch (device globals: no allocation allowed)
__device__ float g_gram[NG][NPAIR];
__device__ float g_sum[NG][GS];
__device__ float g_W[NG][NPAIR];   // lower-tri of inv(chol(Sigma)), k = i*(i+1)/2 + j
__device__ float g_b[NG][GS];      // b_i = sum_{j<=i} W_ij * mu_j

// ---------------------------------------------------------------------------
// Kernel 0: zero the accumulators (graph replays must be deterministic)
// ---------------------------------------------------------------------------
__global__ void zero_kernel() {
    int t = blockIdx.x * blockDim.x + threadIdx.x;
    if (t < NG * NPAIR) ((float*)g_gram)[t] = 0.f;
    if (t < NG * GS)    ((float*)g_sum)[t]  = 0.f;
}

// ---------------------------------------------------------------------------
// Kernel 1: per-group Gram (raw, uncentered) + per-channel sums.
// Grid: (g=16, m=32). 128 threads. Warps 0-1 own pairs 0..67 & sums ch0..7,
// warps 2-3 own pairs 68..135 & sums ch8..15. Each lane-group covers the same
// float2 positions; L1 serves the duplicated loads.
// ---------------------------------------------------------------------------
__global__ __launch_bounds__(128) void stats_kernel(const float* __restrict__ x) {
    const int g = blockIdx.x;
    const int m = blockIdx.y;
    const float* base = x + ((size_t)m * NF + (size_t)g * GS) * HWS;

    const int t    = threadIdx.x;
    const int q    = t & 63;      // float2-position phase
    const int half = t >> 6;      // 0: pairs 0..67, 1: pairs 68..135

    float acc[68];
    float sacc[8];
#pragma unroll
    for (int k = 0; k < 68; k++) acc[k] = 0.f;
#pragma unroll
    for (int k = 0; k < 8;  k++) sacc[k] = 0.f;

    const int NF2 = HWS / 2;  // 1568 float2 positions
    if (half == 0) {
        for (int f = q; f < NF2; f += 64) {
            float2 v[GS];
#pragma unroll
            for (int c = 0; c < GS; c++)
                v[c] = ((const float2*)(base + (size_t)c * HWS))[f];
#pragma unroll
            for (int i = 0; i < GS; i++)
#pragma unroll
                for (int j = 0; j <= i; j++) {
                    const int kk = i * (i + 1) / 2 + j;
                    if (kk < 68) {
                        acc[kk] = fmaf(v[i].x, v[j].x, acc[kk]);
                        acc[kk] = fmaf(v[i].y, v[j].y, acc[kk]);
                    }
                }
#pragma unroll
            for (int c = 0; c < 8; c++) sacc[c] += v[c].x + v[c].y;
        }
    } else {
        for (int f = q; f < NF2; f += 64) {
            float2 v[GS];
#pragma unroll
            for (int c = 0; c < GS; c++)
                v[c] = ((const float2*)(base + (size_t)c * HWS))[f];
#pragma unroll
            for (int i = 0; i < GS; i++)
#pragma unroll
                for (int j = 0; j <= i; j++) {
                    const int kk = i * (i + 1) / 2 + j;
                    if (kk >= 68) {
                        acc[kk - 68] = fmaf(v[i].x, v[j].x, acc[kk - 68]);
                        acc[kk - 68] = fmaf(v[i].y, v[j].y, acc[kk - 68]);
                    }
                }
#pragma unroll
            for (int c = 0; c < 8; c++) sacc[c] += v[c + 8].x + v[c + 8].y;
        }
    }

    // warp reduce (all lanes in a warp hold the same pair layout)
#pragma unroll
    for (int k = 0; k < 68; k++)
#pragma unroll
        for (int s = 16; s > 0; s >>= 1)
            acc[k] += __shfl_xor_sync(0xFFFFFFFFu, acc[k], s);
#pragma unroll
    for (int k = 0; k < 8; k++)
#pragma unroll
        for (int s = 16; s > 0; s >>= 1)
            sacc[k] += __shfl_xor_sync(0xFFFFFFFFu, sacc[k], s);

    __shared__ float red[4][76];
    const int wid  = t >> 5;
    const int lane = t & 31;
    if (lane == 0) {
#pragma unroll
        for (int k = 0; k < 68; k++) red[wid][k] = acc[k];
#pragma unroll
        for (int k = 0; k < 8;  k++) red[wid][68 + k] = sacc[k];
    }
    __syncthreads();

    for (int idx = t; idx < 152; idx += 128) {
        const int hh = idx / 76;
        const int k  = idx % 76;
        const float val = red[2 * hh][k] + red[2 * hh + 1][k];
        if (k < 68) atomicAdd(&g_gram[g][hh * 68 + k], val);
        else        atomicAdd(&g_sum[g][hh * 8 + (k - 68)], val);
    }
}

// ---------------------------------------------------------------------------
// Kernel 2: sigma -> Cholesky -> triangular inverse -> (W, b). 16 threads.
// ---------------------------------------------------------------------------
__global__ void solve_kernel() {
    const int g = threadIdx.x;
    if (g >= NG) return;

    const double n = (double)NTOT;
    double S[GS];
    for (int i = 0; i < GS; i++) S[i] = (double)g_sum[g][i];

    double sig[GS][GS];
    for (int i = 0; i < GS; i++)
        for (int j = 0; j <= i; j++) {
            const int k = i * (i + 1) / 2 + j;
            double G = (double)g_gram[g][k];
            double sh = (G - S[i] * S[j] / n) / (n - 1.0);
            double v = (1.0 - 1e-6) * sh + (i == j ? 1e-6 : 0.0);
            sig[i][j] = v;
            sig[j][i] = v;
        }

    // Cholesky: sig = T * T^T, T lower
    double T[GS][GS];
    for (int j = 0; j < GS; j++) {
        double d = sig[j][j];
        for (int k = 0; k < j; k++) d -= T[j][k] * T[j][k];
        T[j][j] = sqrt(d);
        for (int i = j + 1; i < GS; i++) {
            double s = sig[i][j];
            for (int k = 0; k < j; k++) s -= T[i][k] * T[j][k];
            T[i][j] = s / T[j][j];
        }
    }

    // W = T^{-1} (lower triangular), forward substitution per column
    double W[GS][GS];
    for (int j = 0; j < GS; j++) {
        for (int i = 0; i < GS; i++) W[i][j] = 0.0;
        W[j][j] = 1.0 / T[j][j];
        for (int i = j + 1; i < GS; i++) {
            double s = 0.0;
            for (int k = j; k < i; k++) s += T[i][k] * W[k][j];
            W[i][j] = -s / T[i][i];
        }
    }

    for (int i = 0; i < GS; i++)
        for (int j = 0; j <= i; j++)
            g_W[g][i * (i + 1) / 2 + j] = (float)W[i][j];

    for (int i = 0; i < GS; i++) {
        double b = 0.0;
        for (int j = 0; j <= i; j++) b += W[i][j] * (S[j] / n);
        g_b[g][i] = (float)b;
    }
}

// ---------------------------------------------------------------------------
// Kernel 3: y = W*(x - mu) = W*x - b, triangular. Grid (g=16, m=32), 128 thr.
// float4 vectorized; v/y tiles live in registers; W/b in shared (broadcast LDS).
// ---------------------------------------------------------------------------
__global__ __launch_bounds__(128) void whiten_kernel(const float* __restrict__ x,
                                                     float* __restrict__ out) {
    const int g = blockIdx.x;
    const int m = blockIdx.y;

    __shared__ float sW[NPAIR];
    __shared__ float sb[GS];
    for (int i = threadIdx.x; i < NPAIR + GS; i += 128) {
        if (i < NPAIR) sW[i] = g_W[g][i];
        else           sb[i - NPAIR] = g_b[g][i - NPAIR];
    }
    __syncthreads();

    const size_t base = ((size_t)m * NF + (size_t)g * GS) * HWS;
    const int NF4 = HWS / 4;  // 784

    for (int f = threadIdx.x; f < NF4; f += 128) {
        float4 v[GS];
#pragma unroll
        for (int c = 0; c < GS; c++)
            v[c] = ((const float4*)(x + base + (size_t)c * HWS))[f];

        float4 y[GS];
#pragma unroll
        for (int i = 0; i < GS; i++) {
            const float b = sb[i];
            y[i].x = -b; y[i].y = -b; y[i].z = -b; y[i].w = -b;
#pragma unroll
            for (int j = 0; j <= i; j++) {
                const float w = sW[i * (i + 1) / 2 + j];
                y[i].x = fmaf(w, v[j].x, y[i].x);
                y[i].y = fmaf(w, v[j].y, y[i].y);
                y[i].z = fmaf(w, v[j].z, y[i].z);
                y[i].w = fmaf(w, v[j].w, y[i].w);
            }
        }

#pragma unroll
        for (int c = 0; c < GS; c++)
            ((float4*)(out + base + (size_t)c * HWS))[f] = y[c];
    }
}

// ---------------------------------------------------------------------------
extern "C" void kernel_launch(void* const* d_in, const int* in_sizes, int n_in,
                              void* d_out, int out_size) {
    const float* x = (const float*)d_in[0];
    float* out = (float*)d_out;

    zero_kernel<<<10, 256>>>();
    dim3 grid(NG, MB);
    stats_kernel<<<grid, 128>>>(x);
    solve_kernel<<<1, 16>>>();
    whiten_kernel<<<grid, 128>>>(x, out);
}

// round 3
// speedup vs baseline: 3.2042x; 3.2042x over previous
#include <cuda_runtime.h>

#define NF  256
#define GS  16
#define NG  16
#define HWS 3136        // 56*56
#define MB  32
#define NTOT (MB*HWS)   // 100352
#define NPAIR 136       // 16*17/2
#define NF2  (HWS/2)    // 1568 float2 positions
#define NF4  (HWS/4)    // 784  float4 positions

typedef unsigned long long u64;

// Scratch (device globals: no allocation allowed)
__device__ float g_part[NG][MB][152];   // per (g,m) block: 136 gram pairs + 16 channel sums
__device__ float g_W[NG][NPAIR];        // lower-tri inv(chol(Sigma)), k = i*(i+1)/2 + j
__device__ float g_b[NG][GS];           // b_i = sum_{j<=i} W_ij * mu_j

// ---------------------------------------------------------------------------
// packed f32x2 helpers
// ---------------------------------------------------------------------------
__device__ __forceinline__ u64 ffma2(u64 a, u64 b, u64 c) {
    u64 d;
    asm("fma.rn.f32x2 %0, %1, %2, %3;" : "=l"(d) : "l"(a), "l"(b), "l"(c));
    return d;
}
__device__ __forceinline__ float2 u2f2(u64 v) {
    float2 f;
    asm("mov.b64 {%0, %1}, %2;" : "=f"(f.x), "=f"(f.y) : "l"(v));
    return f;
}

// ---------------------------------------------------------------------------
// Kernel 1: per-group raw Gram + channel sums, per (g, m) block.
// 4 warps; warp W owns pairs [34W, 34W+34) (compile-time pruned) and channel
// sums 4W..4W+3. Every warp streams all 16 channels (x4 dup, L1-served).
// Packed f32x2 FMA halves the FMA issue count. No atomics: block partials.
// ---------------------------------------------------------------------------
template<int W>
__device__ __forceinline__ void accum_warp(const float* __restrict__ base,
                                           int lane, float* __restrict__ part) {
    u64 acc[34];
    float s[4];
#pragma unroll
    for (int k = 0; k < 34; k++) acc[k] = 0ull;
#pragma unroll
    for (int c = 0; c < 4; c++) s[c] = 0.f;

    for (int f = lane; f < NF2; f += 32) {   // exactly 49 iterations
        u64 v[GS];
#pragma unroll
        for (int c = 0; c < GS; c++)
            v[c] = ((const u64*)(base + (size_t)c * HWS))[f];
#pragma unroll
        for (int i = 0; i < GS; i++)
#pragma unroll
            for (int j = 0; j <= i; j++) {
                const int k = i * (i + 1) / 2 + j;
                if (k >= 34 * W && k < 34 * W + 34)
                    acc[k - 34 * W] = ffma2(v[i], v[j], acc[k - 34 * W]);
            }
#pragma unroll
        for (int c = 0; c < 4; c++) {
            float2 f2 = u2f2(v[4 * W + c]);
            s[c] += f2.x + f2.y;
        }
    }

    // warp reduce + write partials (pairs disjoint per warp -> no cross-warp work)
#pragma unroll
    for (int k = 0; k < 34; k++) {
        float2 f2 = u2f2(acc[k]);
        float gsum = f2.x + f2.y;
#pragma unroll
        for (int sh = 16; sh > 0; sh >>= 1)
            gsum += __shfl_xor_sync(0xFFFFFFFFu, gsum, sh);
        if (lane == 0) part[34 * W + k] = gsum;
    }
#pragma unroll
    for (int c = 0; c < 4; c++) {
        float v = s[c];
#pragma unroll
        for (int sh = 16; sh > 0; sh >>= 1)
            v += __shfl_xor_sync(0xFFFFFFFFu, v, sh);
        if (lane == 0) part[136 + 4 * W + c] = v;
    }
}

__global__ __launch_bounds__(128) void stats_kernel(const float* __restrict__ x) {
    const int g = blockIdx.x;
    const int m = blockIdx.y;
    const float* base = x + ((size_t)m * NF + (size_t)g * GS) * HWS;
    const int wid  = threadIdx.x >> 5;
    const int lane = threadIdx.x & 31;
    float* part = g_part[g][m];
    switch (wid) {
        case 0: accum_warp<0>(base, lane, part); break;
        case 1: accum_warp<1>(base, lane, part); break;
        case 2: accum_warp<2>(base, lane, part); break;
        case 3: accum_warp<3>(base, lane, part); break;
    }
}

// ---------------------------------------------------------------------------
// Kernel 2: reduce partials -> sigma -> Cholesky -> inverse -> (W, b).
// One warp per group (512 threads). fp32 throughout (matches fp32 reference).
// Lane-parallel Cholesky; column-parallel forward substitution for T^{-1}.
// ---------------------------------------------------------------------------
__global__ __launch_bounds__(512) void solve_kernel() {
    __shared__ float a [NG][GS][GS + 1];   // sigma, then Cholesky T in lower part
    __shared__ float w [NG][GS][GS + 1];   // T^{-1}
    __shared__ float mu[NG][GS];

    const int g    = threadIdx.x >> 5;
    const int lane = threadIdx.x & 31;
    const float n = (float)NTOT;

    // per-channel means
    if (lane < GS) {
        float s = 0.f;
        for (int m = 0; m < MB; m++) s += g_part[g][m][136 + lane];
        mu[g][lane] = s / n;
    }
    __syncwarp();

    // sigma (both triangles), reducing the 32 block partials from gmem (L2-hot)
    for (int idx = lane; idx < 256; idx += 32) {
        const int i = idx >> 4, j = idx & 15;
        const int ii = i > j ? i : j;
        const int jj = i > j ? j : i;
        const int e = ii * (ii + 1) / 2 + jj;
        float G = 0.f;
        for (int m = 0; m < MB; m++) G += g_part[g][m][e];
        float sh = (G - n * mu[g][i] * mu[g][j]) / (n - 1.0f);
        a[g][i][j] = (1.0f - 1e-6f) * sh + ((i == j) ? 1e-6f : 0.0f);
    }
    __syncwarp();

    // Cholesky in-place (lower), lane i owns row i
    for (int j = 0; j < GS; j++) {
        if (lane == j) a[g][j][j] = sqrtf(a[g][j][j]);
        __syncwarp();
        const float tjj = a[g][j][j];
        if (lane > j && lane < GS) a[g][lane][j] /= tjj;
        __syncwarp();
        if (lane > j && lane < GS) {
            const float lij = a[g][lane][j];
            for (int k = j + 1; k <= lane; k++)
                a[g][lane][k] -= lij * a[g][k][j];
        }
        __syncwarp();
    }

    // W = T^{-1}: lane j computes column j by forward substitution
    if (lane < GS) {
        const int j = lane;
        w[g][j][j] = 1.0f / a[g][j][j];
        for (int i = j + 1; i < GS; i++) {
            float s = 0.f;
            for (int k = j; k < i; k++) s += a[g][i][k] * w[g][k][j];
            w[g][i][j] = -s / a[g][i][i];
        }
        for (int i = j; i < GS; i++)
            g_W[g][i * (i + 1) / 2 + j] = w[g][i][j];
    }
    __syncwarp();

    // b_i = sum_{j<=i} W_ij * mu_j
    if (lane < GS) {
        const int i = lane;
        float b = 0.f;
        for (int j = 0; j <= i; j++) b += w[g][i][j] * mu[g][j];
        g_b[g][i] = b;
    }
}

// ---------------------------------------------------------------------------
// Kernel 3: y = W*x - b (triangular). Store each y_i immediately -> ~85 regs
// instead of 248 -> 4-5 blocks/SM residency to hide the 16 LDG.128 latencies.
// ---------------------------------------------------------------------------
__global__ __launch_bounds__(128, 4) void whiten_kernel(const float* __restrict__ x,
                                                        float* __restrict__ out) {
    const int g = blockIdx.x;
    const int m = blockIdx.y;

    __shared__ float sW[NPAIR];
    __shared__ float sb[GS];
    for (int i = threadIdx.x; i < NPAIR + GS; i += 128) {
        if (i < NPAIR) sW[i] = g_W[g][i];
        else           sb[i - NPAIR] = g_b[g][i - NPAIR];
    }
    __syncthreads();

    const size_t base = ((size_t)m * NF + (size_t)g * GS) * HWS;

    for (int f = threadIdx.x; f < NF4; f += 128) {
        float4 v[GS];
#pragma unroll
        for (int c = 0; c < GS; c++)
            v[c] = ((const float4*)(x + base + (size_t)c * HWS))[f];

#pragma unroll
        for (int i = 0; i < GS; i++) {
            const float b = sb[i];
            float4 y = make_float4(-b, -b, -b, -b);
#pragma unroll
            for (int j = 0; j <= i; j++) {
                const float w = sW[i * (i + 1) / 2 + j];
                y.x = fmaf(w, v[j].x, y.x);
                y.y = fmaf(w, v[j].y, y.y);
                y.z = fmaf(w, v[j].z, y.z);
                y.w = fmaf(w, v[j].w, y.w);
            }
            ((float4*)(out + base + (size_t)i * HWS))[f] = y;
        }
    }
}

// ---------------------------------------------------------------------------
extern "C" void kernel_launch(void* const* d_in, const int* in_sizes, int n_in,
                              void* d_out, int out_size) {
    const float* x = (const float*)d_in[0];
    float* out = (float*)d_out;

    dim3 grid(NG, MB);
    stats_kernel<<<grid, 128>>>(x);
    solve_kernel<<<1, 512>>>();
    whiten_kernel<<<grid, 128>>>(x, out);
}